// round 2
// baseline (speedup 1.0000x reference)
#include <cuda_runtime.h>
#include <cuda_bf16.h>
#include <math_constants.h>

// Problem shape (fixed by the dataset):
//   x     [16384, 512]  fp32
//   W     [512, 256]    fp32
//   means [1000, 256]   fp32 (rows L2-normalized)
//   t     scalar (ignored)
//   out   [16384, 1000] fp32 one-hot of argmax_j (x@W) . means_j
//
// Normalization of feats is a positive per-row scale -> argmax-invariant -> skipped.

#define NS   16384
#define DIN  512
#define NF   256
#define NC   1000

__device__ int g_argmax[NS];

// SMEM layout (dynamic):
//   featsT[256][128]  : 131072 B   (featsT[feat][row_local])
//   xs    [16][128]   :   8192 B   (phase1 A tile, transposed)  -- reused as ms in phase2
//   ws    [16][64]    :   4096 B   (phase1 B tile)
#define SMEM_BYTES (131072 + 8192 + 4096)

__global__ void __launch_bounds__(256, 1)
fused_argmax_kernel(const float* __restrict__ x,
                    const float* __restrict__ W,
                    const float* __restrict__ means,
                    int* __restrict__ argout)
{
    extern __shared__ float sm[];
    float* featsT = sm;                   // [256][128]
    float* xs     = sm + 256 * 128;       // [16][128]
    float* ws     = xs + 16 * 128;        // [16][64]
    float* ms     = xs;                   // phase2 reuse: [16][128]

    const int tid = threadIdx.x;
    const int tx  = tid & 15;             // column group
    const int ty  = tid >> 4;             // row group
    const int row0 = blockIdx.x * 128;

    // ---------------- Phase 1: feats(128x256) = x(128x512) @ W(512x256) ----------------
    // 4 column-chunks of 64; micro-tile 8 rows x 4 cols per thread.
    for (int ch = 0; ch < 4; ++ch) {
        float acc1[8][4];
        #pragma unroll
        for (int r = 0; r < 8; ++r)
            #pragma unroll
            for (int c = 0; c < 4; ++c) acc1[r][c] = 0.0f;

        for (int kc = 0; kc < DIN; kc += 16) {
            __syncthreads();
            // load x tile transposed: xs[k][row]
            #pragma unroll
            for (int i = 0; i < 2; ++i) {
                int id = tid * 2 + i;           // 0..511
                int r  = id >> 2;               // 0..127
                int q  = id & 3;                // 0..3
                float4 v = *(const float4*)(x + (size_t)(row0 + r) * DIN + kc + q * 4);
                xs[(q * 4 + 0) * 128 + r] = v.x;
                xs[(q * 4 + 1) * 128 + r] = v.y;
                xs[(q * 4 + 2) * 128 + r] = v.z;
                xs[(q * 4 + 3) * 128 + r] = v.w;
            }
            // load W tile: ws[k][c] (row-major, coalesced)
            {
                int k  = tid >> 4;              // 0..15
                int c4 = tid & 15;              // 0..15
                float4 v = *(const float4*)(W + (size_t)(kc + k) * NF + ch * 64 + c4 * 4);
                *(float4*)(ws + k * 64 + c4 * 4) = v;
            }
            __syncthreads();

            #pragma unroll
            for (int kk = 0; kk < 16; ++kk) {
                float a[8], b[4];
                *(float4*)(a)     = *(const float4*)(xs + kk * 128 + ty * 8);
                *(float4*)(a + 4) = *(const float4*)(xs + kk * 128 + ty * 8 + 4);
                *(float4*)(b)     = *(const float4*)(ws + kk * 64 + tx * 4);
                #pragma unroll
                for (int r = 0; r < 8; ++r)
                    #pragma unroll
                    for (int c = 0; c < 4; ++c)
                        acc1[r][c] = fmaf(a[r], b[c], acc1[r][c]);
            }
        }
        // write this 64-col chunk into featsT[feat][row]
        #pragma unroll
        for (int c = 0; c < 4; ++c)
            #pragma unroll
            for (int r = 0; r < 8; ++r)
                featsT[(ch * 64 + tx * 4 + c) * 128 + (ty * 8 + r)] = acc1[r][c];
    }
    __syncthreads();

    // ---------------- Phase 2: scores(128x1000) = feats @ means^T, fused argmax ----------------
    float best[8];
    int   bidx[8];
    #pragma unroll
    for (int r = 0; r < 8; ++r) { best[r] = -CUDART_INF_F; bidx[r] = 0; }

    for (int jt = 0; jt < NC; jt += 128) {
        float acc[8][8];
        #pragma unroll
        for (int r = 0; r < 8; ++r)
            #pragma unroll
            for (int c = 0; c < 8; ++c) acc[r][c] = 0.0f;

        for (int kc = 0; kc < NF; kc += 16) {
            __syncthreads();
            // load means tile transposed: ms[k][j]
            #pragma unroll
            for (int i = 0; i < 2; ++i) {
                int id = tid * 2 + i;           // 0..511
                int j  = id >> 2;               // 0..127
                int q  = id & 3;
                int jg = jt + j;
                float4 v = make_float4(0.f, 0.f, 0.f, 0.f);
                if (jg < NC)
                    v = *(const float4*)(means + (size_t)jg * NF + kc + q * 4);
                ms[(q * 4 + 0) * 128 + j] = v.x;
                ms[(q * 4 + 1) * 128 + j] = v.y;
                ms[(q * 4 + 2) * 128 + j] = v.z;
                ms[(q * 4 + 3) * 128 + j] = v.w;
            }
            __syncthreads();

            #pragma unroll
            for (int kk = 0; kk < 16; ++kk) {
                float a[8], b[8];
                const float* fr = featsT + (kc + kk) * 128 + ty * 8;
                *(float4*)(a)     = *(const float4*)(fr);
                *(float4*)(a + 4) = *(const float4*)(fr + 4);
                const float* mr = ms + kk * 128 + tx * 8;
                *(float4*)(b)     = *(const float4*)(mr);
                *(float4*)(b + 4) = *(const float4*)(mr + 4);
                #pragma unroll
                for (int r = 0; r < 8; ++r)
                    #pragma unroll
                    for (int c = 0; c < 8; ++c)
                        acc[r][c] = fmaf(a[r], b[c], acc[r][c]);
            }
        }

        // running argmax update (strict > keeps the earliest index; c ascends -> j ascends)
        #pragma unroll
        for (int c = 0; c < 8; ++c) {
            int jg = jt + tx * 8 + c;
            if (jg < NC) {
                #pragma unroll
                for (int r = 0; r < 8; ++r) {
                    if (acc[r][c] > best[r]) { best[r] = acc[r][c]; bidx[r] = jg; }
                }
            }
        }
    }

    // reduce across the 16 column-lane groups (tx) sharing the same rows.
    // lane = (ty&1)*16 + tx, so xor offsets {8,4,2,1} stay within the tx group.
    #pragma unroll
    for (int r = 0; r < 8; ++r) {
        float v  = best[r];
        int   id = bidx[r];
        #pragma unroll
        for (int off = 8; off >= 1; off >>= 1) {
            float ov = __shfl_xor_sync(0xffffffffu, v, off);
            int   oi = __shfl_xor_sync(0xffffffffu, id, off);
            if (ov > v || (ov == v && oi < id)) { v = ov; id = oi; }
        }
        if (tx == 0)
            argout[row0 + ty * 8 + r] = id;
    }
}

// One-hot writer. 1000 % 4 == 0 so every float4 stays within one row.
__global__ void onehot_kernel(const int* __restrict__ argmax, float* __restrict__ out)
{
    int t = blockIdx.x * blockDim.x + threadIdx.x;   // 0 .. NS*NC/4-1
    int f = t * 4;
    int row = f / NC;
    int col = f - row * NC;
    int idx = __ldg(argmax + row);
    float4 v;
    v.x = (col + 0 == idx) ? 1.0f : 0.0f;
    v.y = (col + 1 == idx) ? 1.0f : 0.0f;
    v.z = (col + 2 == idx) ? 1.0f : 0.0f;
    v.w = (col + 3 == idx) ? 1.0f : 0.0f;
    *(float4*)(out + f) = v;
}

extern "C" void kernel_launch(void* const* d_in, const int* in_sizes, int n_in,
                              void* d_out, int out_size)
{
    const float* x     = (const float*)d_in[0];
    const float* W     = (const float*)d_in[1];
    const float* means = (const float*)d_in[2];
    // d_in[3] = t, unused
    float* out = (float*)d_out;

    int* argout;
    cudaGetSymbolAddress((void**)&argout, g_argmax);

    static bool attr_set = false;
    if (!attr_set) {
        cudaFuncSetAttribute(fused_argmax_kernel,
                             cudaFuncAttributeMaxDynamicSharedMemorySize, SMEM_BYTES);
        attr_set = true;
    }

    fused_argmax_kernel<<<NS / 128, 256, SMEM_BYTES>>>(x, W, means, argout);

    int total4 = NS * NC / 4;                 // 4,096,000
    onehot_kernel<<<total4 / 256, 256>>>(argout, out);
}